// round 11
// baseline (speedup 1.0000x reference)
#include <cuda_runtime.h>
#include <cuda_fp16.h>
#include <cstdint>

#define ALPHA_ 0.2f
#define LOG2E_ 1.4426950408889634f
#define B_    16
#define N_    1024
#define IND_  128
#define HEADS_ 2
#define HD_   64
#define BH_   (B_*HEADS_)

// Scratch. g_hpT16 layout (uint2 units): [bh][gmt(32)][ks(2)][j(8)][lane(32)]
// uint2 per (d=8j+qr, qm): .x = f16x2{V[m0][d], V[m0+1][d]},
// .y = f16x2{V[m0+8][d], V[m0+9][d]}, m0 = gmt*32 + ks*16 + 2qm.
// (exactly the m16n8k16 B-fragment register pair per lane)
__device__ __align__(16) unsigned int g_hpT16[BH_ * HD_ * 512];
__device__ float g_esrc[BH_ * N_];
__device__ float g_edst[BH_ * N_];

// ---------------------------------------------------------------- helpers
__device__ __forceinline__ float ex2f(float x) {
    float y;
    asm("ex2.approx.ftz.f32 %0, %1;" : "=f"(y) : "f"(x));
    return y;
}
__device__ __forceinline__ uint32_t h2pack(float lo, float hi) {
    uint32_t r;
    asm("cvt.rn.f16x2.f32 %0, %1, %2;" : "=r"(r) : "f"(hi), "f"(lo));
    return r;
}
__device__ __forceinline__ uint32_t smem_u32(const void* p) {
    uint32_t a;
    asm("{ .reg .u64 t; cvta.to.shared.u64 t, %1; cvt.u32.u64 %0, t; }" : "=r"(a) : "l"(p));
    return a;
}
__device__ __forceinline__ void cp16(uint32_t dst, const void* src) {
    asm volatile("cp.async.cg.shared.global [%0], [%1], 16;" :: "r"(dst), "l"(src) : "memory");
}
#define CP_COMMIT() asm volatile("cp.async.commit_group;" ::: "memory")
#define CP_WAIT(n)  asm volatile("cp.async.wait_group %0;" :: "n"(n) : "memory")

__device__ __forceinline__ void mma_tf32(float* c,
                                         uint32_t a0, uint32_t a1, uint32_t a2, uint32_t a3,
                                         uint32_t b0, uint32_t b1) {
    asm volatile(
        "mma.sync.aligned.m16n8k8.row.col.f32.tf32.tf32.f32 "
        "{%0,%1,%2,%3}, {%4,%5,%6,%7}, {%8,%9}, {%0,%1,%2,%3};"
        : "+f"(c[0]), "+f"(c[1]), "+f"(c[2]), "+f"(c[3])
        : "r"(a0), "r"(a1), "r"(a2), "r"(a3), "r"(b0), "r"(b1));
}
__device__ __forceinline__ void mma_f16(float* c,
                                        uint32_t a0, uint32_t a1, uint32_t a2, uint32_t a3,
                                        uint32_t b0, uint32_t b1) {
    asm volatile(
        "mma.sync.aligned.m16n8k16.row.col.f32.f16.f16.f32 "
        "{%0,%1,%2,%3}, {%4,%5,%6,%7}, {%8,%9}, {%0,%1,%2,%3};"
        : "+f"(c[0]), "+f"(c[1]), "+f"(c[2]), "+f"(c[3])
        : "r"(a0), "r"(a1), "r"(a2), "r"(a3), "r"(b0), "r"(b1));
}
// 4-op exp in log2 domain: eL = ed*log2e; p = esL + cb; q = 0.2*esL + cb
__device__ __forceinline__ float wexp4(float eL, float p, float q) {
    float t = p + eL;
    float u = fmaf(ALPHA_, eL, q);
    return ex2f(fmaxf(t, u));
}

// ============================================================================
// Kernel A: hp = h @ W via tf32 mma.sync. CTA = 128 rows x 1 head, 256 thr.
// +0x1000 nudge = round-to-nearest tf32. Epilogue: e_src/e_dst + fragment-
// ordered f16 V. grid (128, 2).  (unchanged from R9/R10)
// ============================================================================
__global__ void __launch_bounds__(256) proj_kernel(const float* __restrict__ h,
                                                   const float* __restrict__ W,
                                                   const float* __restrict__ a) {
    extern __shared__ float sm[];
    float* hA = sm;               // [128][136]
    float* WB = sm + 128 * 136;   // [128][68]
    float* T  = sm;               // epilogue reuse: [128 m][68 d]

    int t = threadIdx.x;
    int head = blockIdx.y;
    int r0 = blockIdx.x * 128;
    int b = r0 >> 10, nb = r0 & 1023;
    int bh = b * HEADS_ + head;

    #pragma unroll
    for (int i = 0; i < 16; i++) {
        int f = t + i * 256;
        int row = f >> 5, c4 = f & 31;
        uint4 v = *(const uint4*)(h + (size_t)(r0 + row) * IND_ + c4 * 4);
        v.x += 0x1000u; v.y += 0x1000u; v.z += 0x1000u; v.w += 0x1000u;
        *(uint4*)(hA + row * 136 + c4 * 4) = v;
    }
    #pragma unroll
    for (int i = 0; i < 8; i++) {
        int f = t + i * 256;
        int k = f >> 4, d4 = f & 15;
        uint4 v = *(const uint4*)(W + (size_t)head * (IND_ * HD_) + k * HD_ + d4 * 4);
        v.x += 0x1000u; v.y += 0x1000u; v.z += 0x1000u; v.w += 0x1000u;
        *(uint4*)(WB + k * 68 + d4 * 4) = v;
    }
    __syncthreads();

    int w = t >> 5, lane = t & 31, qr = lane >> 2, qm = lane & 3;
    int rA = w * 16 + qr;

    float c[8][4];
    #pragma unroll
    for (int j = 0; j < 8; j++)
        #pragma unroll
        for (int q = 0; q < 4; q++) c[j][q] = 0.f;

    #pragma unroll
    for (int ks = 0; ks < 16; ks++) {
        int k0 = ks * 8;
        uint32_t a0 = __float_as_uint(hA[rA * 136 + k0 + qm]);
        uint32_t a1 = __float_as_uint(hA[(rA + 8) * 136 + k0 + qm]);
        uint32_t a2 = __float_as_uint(hA[rA * 136 + k0 + qm + 4]);
        uint32_t a3 = __float_as_uint(hA[(rA + 8) * 136 + k0 + qm + 4]);
        const float* b0r = WB + (k0 + qm) * 68 + qr;
        const float* b1r = WB + (k0 + qm + 4) * 68 + qr;
        #pragma unroll
        for (int j = 0; j < 8; j++) {
            mma_tf32(c[j], a0, a1, a2, a3,
                     __float_as_uint(b0r[8 * j]), __float_as_uint(b1r[8 * j]));
        }
    }

    {
        const float* ah = a + head * (2 * HD_);
        float ps0 = 0.f, ps1 = 0.f, pd0 = 0.f, pd1 = 0.f;
        #pragma unroll
        for (int j = 0; j < 8; j++) {
            float2 as = *(const float2*)(ah + 8 * j + 2 * qm);
            float2 ad = *(const float2*)(ah + HD_ + 8 * j + 2 * qm);
            ps0 += c[j][0] * as.x + c[j][1] * as.y;
            ps1 += c[j][2] * as.x + c[j][3] * as.y;
            pd0 += c[j][0] * ad.x + c[j][1] * ad.y;
            pd1 += c[j][2] * ad.x + c[j][3] * ad.y;
        }
        #pragma unroll
        for (int o = 1; o <= 2; o <<= 1) {
            ps0 += __shfl_xor_sync(0xFFFFFFFFu, ps0, o);
            ps1 += __shfl_xor_sync(0xFFFFFFFFu, ps1, o);
            pd0 += __shfl_xor_sync(0xFFFFFFFFu, pd0, o);
            pd1 += __shfl_xor_sync(0xFFFFFFFFu, pd1, o);
        }
        if (qm == 0) {
            int n = nb + rA;
            g_esrc[(size_t)bh * N_ + n] = ps0;
            g_edst[(size_t)bh * N_ + n] = pd0;
            g_esrc[(size_t)bh * N_ + n + 8] = ps1;
            g_edst[(size_t)bh * N_ + n + 8] = pd1;
        }
    }

    __syncthreads();
    #pragma unroll
    for (int j = 0; j < 8; j++) {
        *(float2*)(T + rA * 68 + 8 * j + 2 * qm)       = make_float2(c[j][0], c[j][1]);
        *(float2*)(T + (rA + 8) * 68 + 8 * j + 2 * qm) = make_float2(c[j][2], c[j][3]);
    }
    __syncthreads();

    {
        // gmt for this CTA's 128 m rows: nb/32 .. nb/32+3
        uint2* gbase = (uint2*)g_hpT16 + (size_t)bh * 16384 + (nb >> 5) * 512;
        #pragma unroll
        for (int i = 0; i < 8; i++) {
            int cidx = t + i * 256;
            int mtl = cidx >> 9, ks = (cidx >> 8) & 1, j = (cidx >> 5) & 7;
            int ln = cidx & 31, lqr = ln >> 2, lqm = ln & 3;
            int d = 8 * j + lqr;
            int m0 = mtl * 32 + ks * 16 + 2 * lqm;
            uint2 u;
            u.x = h2pack(T[m0 * 68 + d], T[(m0 + 1) * 68 + d]);
            u.y = h2pack(T[(m0 + 8) * 68 + d], T[(m0 + 9) * 68 + d]);
            gbase[mtl * 512 + ks * 256 + j * 32 + ln] = u;
        }
    }
}

// ============================================================================
// Kernel C: fp16 mma attention. CTA = 128 n rows x FULL 1024 m, 256 thr =
// 8 warps x 16 rows (no m-split, no combine). V staged in 4-mt chunks (16KB),
// 3 stages, cp.async depth 2, 8 barriers. Ones-column MMA denominator.
// grid (8, 32) = 256 CTAs -> single wave; regs unconstrained (no spills).
// ============================================================================
#define SB_V     0                    // 3 stages x 16384 = 49152
#define SB_EDP   49152                // e_dst * log2e, permuted: 4096 B
#define SB_ESRC  53248                // 512 B
#define SB_RED   53760                // 64 B
#define SMEM_C   53824

__global__ void __launch_bounds__(256) attn_kernel(const float* __restrict__ h_in,
                                                   float* __restrict__ out) {
    extern __shared__ char smc[];
    const uint32_t sb = smem_u32(smc);
    float* edp    = (float*)(smc + SB_EDP);
    float* esrc_s = (float*)(smc + SB_ESRC);
    float* red    = (float*)(smc + SB_RED);

    int t = threadIdx.x, w = t >> 5, lane = t & 31;
    int qr = lane >> 2, qm = lane & 3;
    int bh = blockIdx.y, b = bh >> 1, head = bh & 1;
    int n0 = blockIdx.x * 128;

    // cp.async staging map: 16KB chunk / 256 thr = 64B per thread
    const char* gsrc = (const char*)((const uint2*)g_hpT16 + (size_t)bh * 16384) + t * 64;
    uint32_t sdst = sb + SB_V + t * 64;

    // prologue: stage chunks 0 and 1 (gmt 0-7), one commit each
    #pragma unroll
    for (int pp = 0; pp < 2; pp++) {
        const char* gs = gsrc + (size_t)pp * 16384;
        uint32_t sd = sdst + pp * 16384;
        cp16(sd, gs);       cp16(sd + 16, gs + 16);
        cp16(sd + 32, gs + 32); cp16(sd + 48, gs + 48);
        CP_COMMIT();
    }

    // e_dst -> edp (scaled by log2e, fragment-permuted) + block max
    float4 ed4 = *(const float4*)(g_edst + (size_t)bh * N_ + t * 4);
    ed4.x *= LOG2E_; ed4.y *= LOG2E_; ed4.z *= LOG2E_; ed4.w *= LOG2E_;
    {
        float lm = fmaxf(fmaxf(ed4.x, ed4.y), fmaxf(ed4.z, ed4.w));
        #pragma unroll
        for (int o = 16; o; o >>= 1) lm = fmaxf(lm, __shfl_xor_sync(0xFFFFFFFFu, lm, o));
        if (lane == 0) red[w] = lm;
        float edv[4] = {ed4.x, ed4.y, ed4.z, ed4.w};
        #pragma unroll
        for (int e = 0; e < 4; e++) {
            int m = 4 * t + e;
            int g = m >> 4, q = m & 15;
            int dsti = (q < 8) ? ((q >> 1) * 4 + (q & 1))
                               : ((q - 8) >> 1) * 4 + 2 + (q & 1);
            edp[g * 16 + dsti] = edv[e];
        }
    }
    if (t < 128) esrc_s[t] = g_esrc[(size_t)bh * N_ + n0 + t] * LOG2E_;
    __syncthreads();
    if (t == 0) {
        float m = red[0];
        #pragma unroll
        for (int i = 1; i < 8; i++) m = fmaxf(m, red[i]);
        red[0] = m;
    }
    __syncthreads();
    float MxL = red[0];

    // per-thread row constants (log2 domain); warp w owns rows w*16 .. w*16+15
    int r = w * 16 + qr;
    float esL0 = esrc_s[r], esL1 = esrc_s[r + 8];
    float x0 = esL0 + MxL, x1 = esL1 + MxL;
    float cb0 = -fmaxf(x0, ALPHA_ * x0);
    float cb1 = -fmaxf(x1, ALPHA_ * x1);
    float p0 = esL0 + cb0, q0 = fmaf(ALPHA_, esL0, cb0);
    float p1 = esL1 + cb1, q1 = fmaf(ALPHA_, esL1, cb1);

    float c[9][4];
    #pragma unroll
    for (int j = 0; j < 9; j++)
        #pragma unroll
        for (int q = 0; q < 4; q++) c[j][q] = 0.f;

    const uint32_t ONE2 = 0x3C003C00u;
    const float* edw = edp + 4 * qm;

    for (int p = 0; p < 8; p++) {
        if (p < 7) { CP_WAIT(1); } else { CP_WAIT(0); }
        __syncthreads();   // fresh stage visible AND overwrite-target consumed
        if (p < 6) {
            const char* gs = gsrc + (size_t)(p + 2) * 16384;
            uint32_t sd = sdst + (uint32_t)((p + 2) % 3) * 16384;
            cp16(sd, gs);       cp16(sd + 16, gs + 16);
            cp16(sd + 32, gs + 32); cp16(sd + 48, gs + 48);
            CP_COMMIT();
        }
        const char* stb = smc + SB_V + (p % 3) * 16384;
        #pragma unroll
        for (int mtl = 0; mtl < 4; mtl++) {
            int gmt = p * 4 + mtl;
            const uint2* Vb2 = (const uint2*)(stb + mtl * 4096) + lane;
            #pragma unroll
            for (int ks = 0; ks < 2; ks++) {
                float4 e4 = *(const float4*)(edw + (gmt * 2 + ks) * 16);
                uint32_t a0 = h2pack(wexp4(e4.x, p0, q0), wexp4(e4.y, p0, q0));
                uint32_t a1 = h2pack(wexp4(e4.x, p1, q1), wexp4(e4.y, p1, q1));
                uint32_t a2 = h2pack(wexp4(e4.z, p0, q0), wexp4(e4.w, p0, q0));
                uint32_t a3 = h2pack(wexp4(e4.z, p1, q1), wexp4(e4.w, p1, q1));
                const uint2* bp = Vb2 + ks * 256;
                #pragma unroll
                for (int j = 0; j < 8; j++) {
                    uint2 bb = bp[j * 32];
                    mma_f16(c[j], a0, a1, a2, a3, bb.x, bb.y);
                }
                mma_f16(c[8], a0, a1, a2, a3, ONE2, ONE2);
            }
        }
    }

    // epilogue: each warp owns rows r and r+8 fully (64 d) -> direct store
    {
        float inv0 = 1.0f / c[8][0];
        float inv1 = 1.0f / c[8][2];
        int n_row = n0 + r;
        #pragma unroll
        for (int j = 0; j < 8; j++) {
            int d0 = 8 * j + 2 * qm;
            size_t base0 = ((size_t)(b * N_ + n_row)) * IND_ + head * HD_ + d0;
            float2 hv0 = *(const float2*)(h_in + base0);
            float ox = c[j][0] * inv0 + hv0.x;
            float oy = c[j][1] * inv0 + hv0.y;
            ox = ox > 0.f ? ox : expm1f(ox);
            oy = oy > 0.f ? oy : expm1f(oy);
            *(float2*)(out + base0) = make_float2(ox, oy);

            size_t base1 = base0 + (size_t)8 * IND_;
            float2 hv1 = *(const float2*)(h_in + base1);
            float oz = c[j][2] * inv1 + hv1.x;
            float ow = c[j][3] * inv1 + hv1.y;
            oz = oz > 0.f ? oz : expm1f(oz);
            ow = ow > 0.f ? ow : expm1f(ow);
            *(float2*)(out + base1) = make_float2(oz, ow);
        }
    }
}

// ============================================================================
extern "C" void kernel_launch(void* const* d_in, const int* in_sizes, int n_in,
                              void* d_out, int out_size) {
    const float* h = (const float*)d_in[0];
    const float* W = (const float*)d_in[1];
    const float* a = (const float*)d_in[2];
    float* out = (float*)d_out;

    const int smemA = (128 * 136 + 128 * 68) * 4;   // 104448 B
    cudaFuncSetAttribute(proj_kernel, cudaFuncAttributeMaxDynamicSharedMemorySize, smemA);
    cudaFuncSetAttribute(attn_kernel, cudaFuncAttributeMaxDynamicSharedMemorySize, SMEM_C);

    proj_kernel<<<dim3(128, 2), 256, smemA>>>(h, W, a);
    attn_kernel<<<dim3(8, 32), 256, SMEM_C>>>(h, out);
    (void)in_sizes; (void)n_in; (void)out_size;
}

// round 12
// speedup vs baseline: 1.0553x; 1.0553x over previous
#include <cuda_runtime.h>
#include <cuda_fp16.h>
#include <cstdint>

#define ALPHA_ 0.2f
#define LOG2E_ 1.4426950408889634f
#define B_    16
#define N_    1024
#define IND_  128
#define HEADS_ 2
#define HD_   64
#define BH_   (B_*HEADS_)

// Scratch. g_hpT16 layout (uint2 units): [bh][gmt(32)][ks(2)][j(8)][lane(32)]
// uint2 per (d=8j+qr, qm): .x = f16x2{V[m0][d], V[m0+1][d]},
// .y = f16x2{V[m0+8][d], V[m0+9][d]}, m0 = gmt*32 + ks*16 + 2qm.
__device__ __align__(16) unsigned int g_hpT16[BH_ * HD_ * 512];
__device__ float g_esrc[BH_ * N_];
__device__ float g_edst[BH_ * N_];

// ---------------------------------------------------------------- helpers
__device__ __forceinline__ uint32_t h2pack(float lo, float hi) {
    uint32_t r;
    asm("cvt.rn.f16x2.f32 %0, %1, %2;" : "=r"(r) : "f"(hi), "f"(lo));
    return r;
}
__device__ __forceinline__ uint32_t hadd2(uint32_t a, uint32_t b) {
    uint32_t r; asm("add.rn.f16x2 %0, %1, %2;" : "=r"(r) : "r"(a), "r"(b)); return r;
}
__device__ __forceinline__ uint32_t hfma2(uint32_t a, uint32_t b, uint32_t c) {
    uint32_t r; asm("fma.rn.f16x2 %0, %1, %2, %3;" : "=r"(r) : "r"(a), "r"(b), "r"(c)); return r;
}
__device__ __forceinline__ uint32_t hmax2(uint32_t a, uint32_t b) {
    uint32_t r; asm("max.f16x2 %0, %1, %2;" : "=r"(r) : "r"(a), "r"(b)); return r;
}
__device__ __forceinline__ uint32_t hex2x2(uint32_t a) {
    uint32_t r; asm("ex2.approx.f16x2 %0, %1;" : "=r"(r) : "r"(a)); return r;
}
__device__ __forceinline__ uint32_t smem_u32(const void* p) {
    uint32_t a;
    asm("{ .reg .u64 t; cvta.to.shared.u64 t, %1; cvt.u32.u64 %0, t; }" : "=r"(a) : "l"(p));
    return a;
}
__device__ __forceinline__ void cp16(uint32_t dst, const void* src) {
    asm volatile("cp.async.cg.shared.global [%0], [%1], 16;" :: "r"(dst), "l"(src) : "memory");
}
#define CP_COMMIT() asm volatile("cp.async.commit_group;" ::: "memory")
#define CP_WAIT(n)  asm volatile("cp.async.wait_group %0;" :: "n"(n) : "memory")

__device__ __forceinline__ void mma_tf32(float* c,
                                         uint32_t a0, uint32_t a1, uint32_t a2, uint32_t a3,
                                         uint32_t b0, uint32_t b1) {
    asm volatile(
        "mma.sync.aligned.m16n8k8.row.col.f32.tf32.tf32.f32 "
        "{%0,%1,%2,%3}, {%4,%5,%6,%7}, {%8,%9}, {%0,%1,%2,%3};"
        : "+f"(c[0]), "+f"(c[1]), "+f"(c[2]), "+f"(c[3])
        : "r"(a0), "r"(a1), "r"(a2), "r"(a3), "r"(b0), "r"(b1));
}
__device__ __forceinline__ void mma_f16(float* c,
                                        uint32_t a0, uint32_t a1, uint32_t a2, uint32_t a3,
                                        uint32_t b0, uint32_t b1) {
    asm volatile(
        "mma.sync.aligned.m16n8k16.row.col.f32.f16.f16.f32 "
        "{%0,%1,%2,%3}, {%4,%5,%6,%7}, {%8,%9}, {%0,%1,%2,%3};"
        : "+f"(c[0]), "+f"(c[1]), "+f"(c[2]), "+f"(c[3])
        : "r"(a0), "r"(a1), "r"(a2), "r"(a3), "r"(b0), "r"(b1));
}

// ============================================================================
// Kernel A: hp = h @ W via tf32 mma.sync. CTA = 128 rows x 1 head, 256 thr.
// +0x1000 nudge = round-to-nearest tf32. Epilogue: e_src/e_dst + fragment-
// ordered f16 V. grid (128, 2).  (unchanged from R11)
// ============================================================================
__global__ void __launch_bounds__(256) proj_kernel(const float* __restrict__ h,
                                                   const float* __restrict__ W,
                                                   const float* __restrict__ a) {
    extern __shared__ float sm[];
    float* hA = sm;               // [128][136]
    float* WB = sm + 128 * 136;   // [128][68]
    float* T  = sm;               // epilogue reuse: [128 m][68 d]

    int t = threadIdx.x;
    int head = blockIdx.y;
    int r0 = blockIdx.x * 128;
    int b = r0 >> 10, nb = r0 & 1023;
    int bh = b * HEADS_ + head;

    #pragma unroll
    for (int i = 0; i < 16; i++) {
        int f = t + i * 256;
        int row = f >> 5, c4 = f & 31;
        uint4 v = *(const uint4*)(h + (size_t)(r0 + row) * IND_ + c4 * 4);
        v.x += 0x1000u; v.y += 0x1000u; v.z += 0x1000u; v.w += 0x1000u;
        *(uint4*)(hA + row * 136 + c4 * 4) = v;
    }
    #pragma unroll
    for (int i = 0; i < 8; i++) {
        int f = t + i * 256;
        int k = f >> 4, d4 = f & 15;
        uint4 v = *(const uint4*)(W + (size_t)head * (IND_ * HD_) + k * HD_ + d4 * 4);
        v.x += 0x1000u; v.y += 0x1000u; v.z += 0x1000u; v.w += 0x1000u;
        *(uint4*)(WB + k * 68 + d4 * 4) = v;
    }
    __syncthreads();

    int w = t >> 5, lane = t & 31, qr = lane >> 2, qm = lane & 3;
    int rA = w * 16 + qr;

    float c[8][4];
    #pragma unroll
    for (int j = 0; j < 8; j++)
        #pragma unroll
        for (int q = 0; q < 4; q++) c[j][q] = 0.f;

    #pragma unroll
    for (int ks = 0; ks < 16; ks++) {
        int k0 = ks * 8;
        uint32_t a0 = __float_as_uint(hA[rA * 136 + k0 + qm]);
        uint32_t a1 = __float_as_uint(hA[(rA + 8) * 136 + k0 + qm]);
        uint32_t a2 = __float_as_uint(hA[rA * 136 + k0 + qm + 4]);
        uint32_t a3 = __float_as_uint(hA[(rA + 8) * 136 + k0 + qm + 4]);
        const float* b0r = WB + (k0 + qm) * 68 + qr;
        const float* b1r = WB + (k0 + qm + 4) * 68 + qr;
        #pragma unroll
        for (int j = 0; j < 8; j++) {
            mma_tf32(c[j], a0, a1, a2, a3,
                     __float_as_uint(b0r[8 * j]), __float_as_uint(b1r[8 * j]));
        }
    }

    {
        const float* ah = a + head * (2 * HD_);
        float ps0 = 0.f, ps1 = 0.f, pd0 = 0.f, pd1 = 0.f;
        #pragma unroll
        for (int j = 0; j < 8; j++) {
            float2 as = *(const float2*)(ah + 8 * j + 2 * qm);
            float2 ad = *(const float2*)(ah + HD_ + 8 * j + 2 * qm);
            ps0 += c[j][0] * as.x + c[j][1] * as.y;
            ps1 += c[j][2] * as.x + c[j][3] * as.y;
            pd0 += c[j][0] * ad.x + c[j][1] * ad.y;
            pd1 += c[j][2] * ad.x + c[j][3] * ad.y;
        }
        #pragma unroll
        for (int o = 1; o <= 2; o <<= 1) {
            ps0 += __shfl_xor_sync(0xFFFFFFFFu, ps0, o);
            ps1 += __shfl_xor_sync(0xFFFFFFFFu, ps1, o);
            pd0 += __shfl_xor_sync(0xFFFFFFFFu, pd0, o);
            pd1 += __shfl_xor_sync(0xFFFFFFFFu, pd1, o);
        }
        if (qm == 0) {
            int n = nb + rA;
            g_esrc[(size_t)bh * N_ + n] = ps0;
            g_edst[(size_t)bh * N_ + n] = pd0;
            g_esrc[(size_t)bh * N_ + n + 8] = ps1;
            g_edst[(size_t)bh * N_ + n + 8] = pd1;
        }
    }

    __syncthreads();
    #pragma unroll
    for (int j = 0; j < 8; j++) {
        *(float2*)(T + rA * 68 + 8 * j + 2 * qm)       = make_float2(c[j][0], c[j][1]);
        *(float2*)(T + (rA + 8) * 68 + 8 * j + 2 * qm) = make_float2(c[j][2], c[j][3]);
    }
    __syncthreads();

    {
        uint2* gbase = (uint2*)g_hpT16 + (size_t)bh * 16384 + (nb >> 5) * 512;
        #pragma unroll
        for (int i = 0; i < 8; i++) {
            int cidx = t + i * 256;
            int mtl = cidx >> 9, ks = (cidx >> 8) & 1, j = (cidx >> 5) & 7;
            int ln = cidx & 31, lqr = ln >> 2, lqm = ln & 3;
            int d = 8 * j + lqr;
            int m0 = mtl * 32 + ks * 16 + 2 * lqm;
            uint2 u;
            u.x = h2pack(T[m0 * 68 + d], T[(m0 + 1) * 68 + d]);
            u.y = h2pack(T[(m0 + 8) * 68 + d], T[(m0 + 9) * 68 + d]);
            gbase[mtl * 512 + ks * 256 + j * 32 + ln] = u;
        }
    }
}

// ============================================================================
// Kernel C: fp16 mma attention, f16x2 packed exp pipeline. CTA = 128 n rows x
// full 1024 m, 8 warps x 16 rows. V staged in 4-mt chunks, 3 stages. e_dst in
// smem as f16x2 fragment-ordered pairs -> exp output IS the A-fragment.
// Ones-column MMA denominator. grid (8, 32).
// ============================================================================
#define SB_V     0                    // 3 stages x 16384 = 49152
#define SB_EDP   49152                // e_dst*log2e as f16x2 pairs: 2048 B
#define SB_ESRC  51200                // 512 B
#define SB_RED   51712                // 64 B
#define SMEM_C   51776

__global__ void __launch_bounds__(256) attn_kernel(const float* __restrict__ h_in,
                                                   float* __restrict__ out) {
    extern __shared__ char smc[];
    const uint32_t sb = smem_u32(smc);
    uint32_t* edph = (uint32_t*)(smc + SB_EDP);
    float* esrc_s  = (float*)(smc + SB_ESRC);
    float* red     = (float*)(smc + SB_RED);

    int t = threadIdx.x, w = t >> 5, lane = t & 31;
    int qr = lane >> 2, qm = lane & 3;
    int bh = blockIdx.y, b = bh >> 1, head = bh & 1;
    int n0 = blockIdx.x * 128;

    // cp.async staging map: 16KB chunk / 256 thr = 64B per thread
    const char* gsrc = (const char*)((const uint2*)g_hpT16 + (size_t)bh * 16384) + t * 64;
    uint32_t sdst = sb + SB_V + t * 64;

    #pragma unroll
    for (int pp = 0; pp < 2; pp++) {
        const char* gs = gsrc + (size_t)pp * 16384;
        uint32_t sd = sdst + pp * 16384;
        cp16(sd, gs);       cp16(sd + 16, gs + 16);
        cp16(sd + 32, gs + 32); cp16(sd + 48, gs + 48);
        CP_COMMIT();
    }

    // e_dst -> edph (scaled by log2e, f16x2 pairs in fragment slot order)
    float4 ed4 = *(const float4*)(g_edst + (size_t)bh * N_ + t * 4);
    ed4.x *= LOG2E_; ed4.y *= LOG2E_; ed4.z *= LOG2E_; ed4.w *= LOG2E_;
    {
        float lm = fmaxf(fmaxf(ed4.x, ed4.y), fmaxf(ed4.z, ed4.w));
        #pragma unroll
        for (int o = 16; o; o >>= 1) lm = fmaxf(lm, __shfl_xor_sync(0xFFFFFFFFu, lm, o));
        if (lane == 0) red[w] = lm;
        // pairs: A={m4t,m4t+1}, B={m4t+2,m4t+3}; slot within 8-u32 group:
        // pairA pp=2*(t&3): slot = pp<4 ? 2pp : 2(pp-4)+1 ; pairB pp+1 likewise
        int g = t >> 2, tm = t & 3;
        int slotA = (tm < 2) ? 4 * tm : 4 * (tm - 2) + 1;
        int slotB = (tm < 2) ? 4 * tm + 2 : 4 * (tm - 2) + 3;
        edph[g * 8 + slotA] = h2pack(ed4.x, ed4.y);
        edph[g * 8 + slotB] = h2pack(ed4.z, ed4.w);
    }
    if (t < 128) esrc_s[t] = g_esrc[(size_t)bh * N_ + n0 + t] * LOG2E_;
    __syncthreads();
    if (t == 0) {
        float m = red[0];
        #pragma unroll
        for (int i = 1; i < 8; i++) m = fmaxf(m, red[i]);
        red[0] = m;
    }
    __syncthreads();
    float MxL = red[0];

    // per-thread row constants -> packed f16x2
    int r = w * 16 + qr;
    float esL0 = esrc_s[r], esL1 = esrc_s[r + 8];
    float x0 = esL0 + MxL, x1 = esL1 + MxL;
    float cb0 = -fmaxf(x0, ALPHA_ * x0);
    float cb1 = -fmaxf(x1, ALPHA_ * x1);
    uint32_t P0 = h2pack(esL0 + cb0, esL0 + cb0);
    uint32_t Q0 = h2pack(fmaf(ALPHA_, esL0, cb0), fmaf(ALPHA_, esL0, cb0));
    uint32_t P1 = h2pack(esL1 + cb1, esL1 + cb1);
    uint32_t Q1 = h2pack(fmaf(ALPHA_, esL1, cb1), fmaf(ALPHA_, esL1, cb1));
    const uint32_t HA = 0x32663266u;   // {0.2h, 0.2h}

    float c[9][4];
    #pragma unroll
    for (int j = 0; j < 9; j++)
        #pragma unroll
        for (int q = 0; q < 4; q++) c[j][q] = 0.f;

    const uint32_t ONE2 = 0x3C003C00u;
    const uint32_t* edw = edph + 2 * qm;

    for (int p = 0; p < 8; p++) {
        if (p < 7) { CP_WAIT(1); } else { CP_WAIT(0); }
        __syncthreads();   // fresh stage visible AND overwrite-target consumed
        if (p < 6) {
            const char* gs = gsrc + (size_t)(p + 2) * 16384;
            uint32_t sd = sdst + (uint32_t)((p + 2) % 3) * 16384;
            cp16(sd, gs);       cp16(sd + 16, gs + 16);
            cp16(sd + 32, gs + 32); cp16(sd + 48, gs + 48);
            CP_COMMIT();
        }
        const char* stb = smc + SB_V + (p % 3) * 16384;
        #pragma unroll
        for (int mtl = 0; mtl < 4; mtl++) {
            int gmt = p * 4 + mtl;
            const uint2* Vb2 = (const uint2*)(stb + mtl * 4096) + lane;
            #pragma unroll
            for (int ks = 0; ks < 2; ks++) {
                uint2 e2 = *(const uint2*)(edw + (gmt * 2 + ks) * 8);
                uint32_t a0 = hex2x2(hmax2(hadd2(P0, e2.x), hfma2(HA, e2.x, Q0)));
                uint32_t a1 = hex2x2(hmax2(hadd2(P1, e2.x), hfma2(HA, e2.x, Q1)));
                uint32_t a2 = hex2x2(hmax2(hadd2(P0, e2.y), hfma2(HA, e2.y, Q0)));
                uint32_t a3 = hex2x2(hmax2(hadd2(P1, e2.y), hfma2(HA, e2.y, Q1)));
                const uint2* bp = Vb2 + ks * 256;
                #pragma unroll
                for (int j = 0; j < 8; j++) {
                    uint2 bb = bp[j * 32];
                    mma_f16(c[j], a0, a1, a2, a3, bb.x, bb.y);
                }
                mma_f16(c[8], a0, a1, a2, a3, ONE2, ONE2);
            }
        }
    }

    // epilogue: each warp owns rows r and r+8 fully (64 d) -> direct store
    {
        float inv0 = 1.0f / c[8][0];
        float inv1 = 1.0f / c[8][2];
        int n_row = n0 + r;
        #pragma unroll
        for (int j = 0; j < 8; j++) {
            int d0 = 8 * j + 2 * qm;
            size_t base0 = ((size_t)(b * N_ + n_row)) * IND_ + head * HD_ + d0;
            float2 hv0 = *(const float2*)(h_in + base0);
            float ox = c[j][0] * inv0 + hv0.x;
            float oy = c[j][1] * inv0 + hv0.y;
            ox = ox > 0.f ? ox : expm1f(ox);
            oy = oy > 0.f ? oy : expm1f(oy);
            *(float2*)(out + base0) = make_float2(ox, oy);

            size_t base1 = base0 + (size_t)8 * IND_;
            float2 hv1 = *(const float2*)(h_in + base1);
            float oz = c[j][2] * inv1 + hv1.x;
            float ow = c[j][3] * inv1 + hv1.y;
            oz = oz > 0.f ? oz : expm1f(oz);
            ow = ow > 0.f ? ow : expm1f(ow);
            *(float2*)(out + base1) = make_float2(oz, ow);
        }
    }
}

// ============================================================================
extern "C" void kernel_launch(void* const* d_in, const int* in_sizes, int n_in,
                              void* d_out, int out_size) {
    const float* h = (const float*)d_in[0];
    const float* W = (const float*)d_in[1];
    const float* a = (const float*)d_in[2];
    float* out = (float*)d_out;

    const int smemA = (128 * 136 + 128 * 68) * 4;   // 104448 B
    cudaFuncSetAttribute(proj_kernel, cudaFuncAttributeMaxDynamicSharedMemorySize, smemA);
    cudaFuncSetAttribute(attn_kernel, cudaFuncAttributeMaxDynamicSharedMemorySize, SMEM_C);

    proj_kernel<<<dim3(128, 2), 256, smemA>>>(h, W, a);
    attn_kernel<<<dim3(8, 32), 256, SMEM_C>>>(h, out);
    (void)in_sizes; (void)n_in; (void)out_size;
}